// round 1
// baseline (speedup 1.0000x reference)
#include <cuda_runtime.h>
#include <math.h>

#define NHEADS 8
#define DMODEL 1024
#define DHEAD  128
#define KFDIM  3072
#define NSENT  2048
#define NKNOW  8192

// Scratch for per-head projections (no cudaMalloc allowed).
__device__ float g_S[NHEADS * NSENT * DHEAD];   // 8 MB
__device__ float g_K[NHEADS * NKNOW * DHEAD];   // 32 MB

// ---------------------------------------------------------------------------
// Generic batched tiled SGEMM.
//   C[z][m, n] = scale * sum_k A[z][m, k] * B(z, k, n)  (+ bias[z][n])
//   A: row-major, lda. B: if !TRANS_B row-major [K,N] (ldb = row stride);
//      if TRANS_B, B is stored [N,K] row-major (ldb = row stride) and we
//      read B(k,n) = B[n*ldb + k].
//   C element: C + z*strideC + m*ldc + n.
// Requires M%128==0, N%128==0, K%8==0, pointers 16B aligned, lda/ldb/ldc %4==0.
// ---------------------------------------------------------------------------
#define BM 128
#define BN 128
#define BK 8

template<bool TRANS_B, bool HAS_BIAS>
__global__ __launch_bounds__(256)
void sgemm_kernel(const float* __restrict__ A, const float* __restrict__ B,
                  const float* __restrict__ bias, float* __restrict__ C,
                  int M, int N, int K,
                  int lda, int ldb, int ldc,
                  long strideA, long strideB, long strideBias, long strideC,
                  float scale)
{
    __shared__ float As[BK][BM];
    __shared__ float Bs[BK][BN];

    const int t  = threadIdx.x;          // 0..255
    const int z  = blockIdx.z;
    const int bm0 = blockIdx.y * BM;
    const int bn0 = blockIdx.x * BN;

    const float* Ap = A + (size_t)z * strideA;
    const float* Bp = B + (size_t)z * strideB;
    float*       Cp = C + (size_t)z * strideC;

    // A tile loader: 128 rows x 8 cols, one float4 per thread along k
    const int a_row = t >> 1;            // 0..127
    const int a_col = (t & 1) << 2;      // 0 or 4
    // B tile loader (non-trans): 8 rows x 128 cols, float4 along n
    const int b_row = t >> 5;            // 0..7
    const int b_col = (t & 31) << 2;     // 0..124
    // B tile loader (trans): 128 n-rows, float4 along k
    const int tb_n  = t >> 1;            // 0..127
    const int tb_k  = (t & 1) << 2;      // 0 or 4

    const int tx = t & 15;               // n micro-tile
    const int ty = t >> 4;               // m micro-tile

    float acc[8][8];
#pragma unroll
    for (int i = 0; i < 8; i++)
#pragma unroll
        for (int j = 0; j < 8; j++) acc[i][j] = 0.f;

    for (int k0 = 0; k0 < K; k0 += BK) {
        // --- stage A (transposed into smem: As[k][m]) ---
        float4 av = *(const float4*)(Ap + (size_t)(bm0 + a_row) * lda + k0 + a_col);
        As[a_col + 0][a_row] = av.x;
        As[a_col + 1][a_row] = av.y;
        As[a_col + 2][a_row] = av.z;
        As[a_col + 3][a_row] = av.w;

        // --- stage B (Bs[k][n]) ---
        if (!TRANS_B) {
            float4 bv = *(const float4*)(Bp + (size_t)(k0 + b_row) * ldb + bn0 + b_col);
            *(float4*)&Bs[b_row][b_col] = bv;
        } else {
            float4 bv = *(const float4*)(Bp + (size_t)(bn0 + tb_n) * ldb + k0 + tb_k);
            Bs[tb_k + 0][tb_n] = bv.x;
            Bs[tb_k + 1][tb_n] = bv.y;
            Bs[tb_k + 2][tb_n] = bv.z;
            Bs[tb_k + 3][tb_n] = bv.w;
        }
        __syncthreads();

#pragma unroll
        for (int kk = 0; kk < BK; kk++) {
            float ar[8], br[8];
            *(float4*)(ar)     = *(const float4*)&As[kk][ty * 8];
            *(float4*)(ar + 4) = *(const float4*)&As[kk][ty * 8 + 4];
            *(float4*)(br)     = *(const float4*)&Bs[kk][tx * 8];
            *(float4*)(br + 4) = *(const float4*)&Bs[kk][tx * 8 + 4];
#pragma unroll
            for (int i = 0; i < 8; i++)
#pragma unroll
                for (int j = 0; j < 8; j++)
                    acc[i][j] = fmaf(ar[i], br[j], acc[i][j]);
        }
        __syncthreads();
    }

    // --- epilogue ---
    float bv[8];
    if (HAS_BIAS) {
        const float* bp = bias + (size_t)z * strideBias + bn0 + tx * 8;
#pragma unroll
        for (int j = 0; j < 8; j++) bv[j] = bp[j];
    }
#pragma unroll
    for (int i = 0; i < 8; i++) {
        size_t m = (size_t)(bm0 + ty * 8 + i);
        float* crow = Cp + m * (size_t)ldc + bn0 + tx * 8;
        float4 o0, o1;
        o0.x = acc[i][0] * scale; o0.y = acc[i][1] * scale;
        o0.z = acc[i][2] * scale; o0.w = acc[i][3] * scale;
        o1.x = acc[i][4] * scale; o1.y = acc[i][5] * scale;
        o1.z = acc[i][6] * scale; o1.w = acc[i][7] * scale;
        if (HAS_BIAS) {
            o0.x += bv[0]; o0.y += bv[1]; o0.z += bv[2]; o0.w += bv[3];
            o1.x += bv[4]; o1.y += bv[5]; o1.z += bv[6]; o1.w += bv[7];
        }
        *(float4*)(crow)     = o0;
        *(float4*)(crow + 4) = o1;
    }
}

// ---------------------------------------------------------------------------
// Column softmax over the sentence axis (axis n) of attn[h][n][m], in place.
// One thread per (h, m) column: 2048 strided (coalesced-across-threads) reads
// for online max+sum, then one read+write pass to normalize.
// ---------------------------------------------------------------------------
__global__ void softmax_cols_kernel(float* __restrict__ attn)
{
    const int h = blockIdx.y;
    const int m = blockIdx.x * blockDim.x + threadIdx.x;   // 0..NKNOW-1
    float* p = attn + (size_t)h * NSENT * NKNOW + m;

    float mx = -INFINITY;
    float sum = 0.f;
    for (int n = 0; n < NSENT; n++) {
        float v = p[(size_t)n * NKNOW];
        if (v > mx) {
            sum = sum * __expf(mx - v) + 1.f;
            mx = v;
        } else {
            sum += __expf(v - mx);
        }
    }
    const float inv = 1.f / sum;
    for (int n = 0; n < NSENT; n++) {
        size_t idx = (size_t)n * NKNOW;
        p[idx] = __expf(p[idx] - mx) * inv;
    }
}

// ---------------------------------------------------------------------------
// Launch: S proj -> K proj -> scores -> softmax -> fused
// Output layout: [attn (H*NS*NK floats) | fused (NS*H*KFDIM floats)]
// ---------------------------------------------------------------------------
extern "C" void kernel_launch(void* const* d_in, const int* in_sizes, int n_in,
                              void* d_out, int out_size)
{
    const float* sentences = (const float*)d_in[0];   // [NS, D]
    const float* knowledge = (const float*)d_in[1];   // [NK, KFDIM]
    const float* w_s       = (const float*)d_in[2];   // [H, D, DH]
    const float* b_s       = (const float*)d_in[3];   // [H, DH]
    const float* w_k       = (const float*)d_in[4];   // [H, KFDIM, DH]
    const float* b_k       = (const float*)d_in[5];   // [H, DH]

    float* attn  = (float*)d_out;                               // [H, NS, NK]
    float* fused = (float*)d_out + (size_t)NHEADS * NSENT * NKNOW; // [NS, H*KFDIM]

    float* Sbuf = nullptr;
    float* Kbuf = nullptr;
    cudaGetSymbolAddress((void**)&Sbuf, g_S);
    cudaGetSymbolAddress((void**)&Kbuf, g_K);

    // 1) S = sentences @ w_s[h] + b_s[h]  -> g_S [H, NS, DH]
    {
        dim3 grid(DHEAD / BN, NSENT / BM, NHEADS);
        sgemm_kernel<false, true><<<grid, 256>>>(
            sentences, w_s, b_s, Sbuf,
            NSENT, DHEAD, DMODEL,
            DMODEL, DHEAD, DHEAD,
            0L, (long)DMODEL * DHEAD, (long)DHEAD, (long)NSENT * DHEAD,
            1.0f);
    }
    // 2) K = knowledge @ w_k[h] + b_k[h]  -> g_K [H, NK, DH]
    {
        dim3 grid(DHEAD / BN, NKNOW / BM, NHEADS);
        sgemm_kernel<false, true><<<grid, 256>>>(
            knowledge, w_k, b_k, Kbuf,
            NKNOW, DHEAD, KFDIM,
            KFDIM, DHEAD, DHEAD,
            0L, (long)KFDIM * DHEAD, (long)DHEAD, (long)NKNOW * DHEAD,
            1.0f);
    }
    // 3) scores[h] = (S[h] @ K[h]^T) / sqrt(DH) -> attn region (pre-softmax)
    {
        dim3 grid(NKNOW / BN, NSENT / BM, NHEADS);
        const float scale = 0.08838834764831845f;  // 1/sqrt(128)
        sgemm_kernel<true, false><<<grid, 256>>>(
            Sbuf, Kbuf, nullptr, attn,
            NSENT, NKNOW, DHEAD,
            DHEAD, DHEAD, NKNOW,
            (long)NSENT * DHEAD, (long)NKNOW * DHEAD, 0L, (long)NSENT * NKNOW,
            scale);
    }
    // 4) softmax over the sentence axis, in place
    {
        dim3 grid(NKNOW / 256, NHEADS);
        softmax_cols_kernel<<<grid, 256>>>(attn);
    }
    // 5) fused[n, h*KFDIM + f] = attn[h] @ knowledge
    {
        dim3 grid(KFDIM / BN, NSENT / BM, NHEADS);
        sgemm_kernel<false, false><<<grid, 256>>>(
            attn, knowledge, nullptr, fused,
            NSENT, KFDIM, NKNOW,
            NKNOW, KFDIM, NHEADS * KFDIM,
            (long)NSENT * NKNOW, 0L, 0L, (long)KFDIM,
            1.0f);
    }
}

// round 2
// speedup vs baseline: 1.0003x; 1.0003x over previous
#include <cuda_runtime.h>
#include <math.h>

#define NHEADS 8
#define DMODEL 1024
#define DHEAD  128
#define KFDIM  3072
#define NSENT  2048
#define NKNOW  8192

// Scratch for per-head projections (no cudaMalloc allowed).
__device__ float g_S[NHEADS * NSENT * DHEAD];   // 8 MB
__device__ float g_K[NHEADS * NKNOW * DHEAD];   // 32 MB

// ---------------------------------------------------------------------------
// Generic batched tiled SGEMM.
//   C[z][m, n] = scale * sum_k A[z][m, k] * B(z, k, n)  (+ bias[z][n])
//   A: row-major, lda. B: if !TRANS_B row-major [K,N] (ldb = row stride);
//      if TRANS_B, B is stored [N,K] row-major (ldb = row stride) and we
//      read B(k,n) = B[n*ldb + k].
//   C element: C + z*strideC + m*ldc + n.
// Requires M%128==0, N%128==0, K%8==0, pointers 16B aligned, lda/ldb/ldc %4==0.
// ---------------------------------------------------------------------------
#define BM 128
#define BN 128
#define BK 8

template<bool TRANS_B, bool HAS_BIAS>
__global__ __launch_bounds__(256)
void sgemm_kernel(const float* __restrict__ A, const float* __restrict__ B,
                  const float* __restrict__ bias, float* __restrict__ C,
                  int M, int N, int K,
                  int lda, int ldb, int ldc,
                  long strideA, long strideB, long strideBias, long strideC,
                  float scale)
{
    __shared__ float As[BK][BM];
    __shared__ float Bs[BK][BN];

    const int t  = threadIdx.x;          // 0..255
    const int z  = blockIdx.z;
    const int bm0 = blockIdx.y * BM;
    const int bn0 = blockIdx.x * BN;

    const float* Ap = A + (size_t)z * strideA;
    const float* Bp = B + (size_t)z * strideB;
    float*       Cp = C + (size_t)z * strideC;

    // A tile loader: 128 rows x 8 cols, one float4 per thread along k
    const int a_row = t >> 1;            // 0..127
    const int a_col = (t & 1) << 2;      // 0 or 4
    // B tile loader (non-trans): 8 rows x 128 cols, float4 along n
    const int b_row = t >> 5;            // 0..7
    const int b_col = (t & 31) << 2;     // 0..124
    // B tile loader (trans): 128 n-rows, float4 along k
    const int tb_n  = t >> 1;            // 0..127
    const int tb_k  = (t & 1) << 2;      // 0 or 4

    const int tx = t & 15;               // n micro-tile
    const int ty = t >> 4;               // m micro-tile

    float acc[8][8];
#pragma unroll
    for (int i = 0; i < 8; i++)
#pragma unroll
        for (int j = 0; j < 8; j++) acc[i][j] = 0.f;

    for (int k0 = 0; k0 < K; k0 += BK) {
        // --- stage A (transposed into smem: As[k][m]) ---
        float4 av = *(const float4*)(Ap + (size_t)(bm0 + a_row) * lda + k0 + a_col);
        As[a_col + 0][a_row] = av.x;
        As[a_col + 1][a_row] = av.y;
        As[a_col + 2][a_row] = av.z;
        As[a_col + 3][a_row] = av.w;

        // --- stage B (Bs[k][n]) ---
        if (!TRANS_B) {
            float4 bv = *(const float4*)(Bp + (size_t)(k0 + b_row) * ldb + bn0 + b_col);
            *(float4*)&Bs[b_row][b_col] = bv;
        } else {
            float4 bv = *(const float4*)(Bp + (size_t)(bn0 + tb_n) * ldb + k0 + tb_k);
            Bs[tb_k + 0][tb_n] = bv.x;
            Bs[tb_k + 1][tb_n] = bv.y;
            Bs[tb_k + 2][tb_n] = bv.z;
            Bs[tb_k + 3][tb_n] = bv.w;
        }
        __syncthreads();

#pragma unroll
        for (int kk = 0; kk < BK; kk++) {
            float ar[8], br[8];
            *(float4*)(ar)     = *(const float4*)&As[kk][ty * 8];
            *(float4*)(ar + 4) = *(const float4*)&As[kk][ty * 8 + 4];
            *(float4*)(br)     = *(const float4*)&Bs[kk][tx * 8];
            *(float4*)(br + 4) = *(const float4*)&Bs[kk][tx * 8 + 4];
#pragma unroll
            for (int i = 0; i < 8; i++)
#pragma unroll
                for (int j = 0; j < 8; j++)
                    acc[i][j] = fmaf(ar[i], br[j], acc[i][j]);
        }
        __syncthreads();
    }

    // --- epilogue ---
    float bv[8];
    if (HAS_BIAS) {
        const float* bp = bias + (size_t)z * strideBias + bn0 + tx * 8;
#pragma unroll
        for (int j = 0; j < 8; j++) bv[j] = bp[j];
    }
#pragma unroll
    for (int i = 0; i < 8; i++) {
        size_t m = (size_t)(bm0 + ty * 8 + i);
        float* crow = Cp + m * (size_t)ldc + bn0 + tx * 8;
        float4 o0, o1;
        o0.x = acc[i][0] * scale; o0.y = acc[i][1] * scale;
        o0.z = acc[i][2] * scale; o0.w = acc[i][3] * scale;
        o1.x = acc[i][4] * scale; o1.y = acc[i][5] * scale;
        o1.z = acc[i][6] * scale; o1.w = acc[i][7] * scale;
        if (HAS_BIAS) {
            o0.x += bv[0]; o0.y += bv[1]; o0.z += bv[2]; o0.w += bv[3];
            o1.x += bv[4]; o1.y += bv[5]; o1.z += bv[6]; o1.w += bv[7];
        }
        *(float4*)(crow)     = o0;
        *(float4*)(crow + 4) = o1;
    }
}

// ---------------------------------------------------------------------------
// Column softmax over the sentence axis (axis n) of attn[h][n][m], in place.
// One thread per (h, m) column: 2048 strided (coalesced-across-threads) reads
// for online max+sum, then one read+write pass to normalize.
// ---------------------------------------------------------------------------
__global__ void softmax_cols_kernel(float* __restrict__ attn)
{
    const int h = blockIdx.y;
    const int m = blockIdx.x * blockDim.x + threadIdx.x;   // 0..NKNOW-1
    float* p = attn + (size_t)h * NSENT * NKNOW + m;

    float mx = -INFINITY;
    float sum = 0.f;
    for (int n = 0; n < NSENT; n++) {
        float v = p[(size_t)n * NKNOW];
        if (v > mx) {
            sum = sum * __expf(mx - v) + 1.f;
            mx = v;
        } else {
            sum += __expf(v - mx);
        }
    }
    const float inv = 1.f / sum;
    for (int n = 0; n < NSENT; n++) {
        size_t idx = (size_t)n * NKNOW;
        p[idx] = __expf(p[idx] - mx) * inv;
    }
}

// ---------------------------------------------------------------------------
// Launch: S proj -> K proj -> scores -> softmax -> fused
// Output layout: [attn (H*NS*NK floats) | fused (NS*H*KFDIM floats)]
// ---------------------------------------------------------------------------
extern "C" void kernel_launch(void* const* d_in, const int* in_sizes, int n_in,
                              void* d_out, int out_size)
{
    const float* sentences = (const float*)d_in[0];   // [NS, D]
    const float* knowledge = (const float*)d_in[1];   // [NK, KFDIM]
    const float* w_s       = (const float*)d_in[2];   // [H, D, DH]
    const float* b_s       = (const float*)d_in[3];   // [H, DH]
    const float* w_k       = (const float*)d_in[4];   // [H, KFDIM, DH]
    const float* b_k       = (const float*)d_in[5];   // [H, DH]

    float* attn  = (float*)d_out;                               // [H, NS, NK]
    float* fused = (float*)d_out + (size_t)NHEADS * NSENT * NKNOW; // [NS, H*KFDIM]

    float* Sbuf = nullptr;
    float* Kbuf = nullptr;
    cudaGetSymbolAddress((void**)&Sbuf, g_S);
    cudaGetSymbolAddress((void**)&Kbuf, g_K);

    // 1) S = sentences @ w_s[h] + b_s[h]  -> g_S [H, NS, DH]
    {
        dim3 grid(DHEAD / BN, NSENT / BM, NHEADS);
        sgemm_kernel<false, true><<<grid, 256>>>(
            sentences, w_s, b_s, Sbuf,
            NSENT, DHEAD, DMODEL,
            DMODEL, DHEAD, DHEAD,
            0L, (long)DMODEL * DHEAD, (long)DHEAD, (long)NSENT * DHEAD,
            1.0f);
    }
    // 2) K = knowledge @ w_k[h] + b_k[h]  -> g_K [H, NK, DH]
    {
        dim3 grid(DHEAD / BN, NKNOW / BM, NHEADS);
        sgemm_kernel<false, true><<<grid, 256>>>(
            knowledge, w_k, b_k, Kbuf,
            NKNOW, DHEAD, KFDIM,
            KFDIM, DHEAD, DHEAD,
            0L, (long)KFDIM * DHEAD, (long)DHEAD, (long)NKNOW * DHEAD,
            1.0f);
    }
    // 3) scores[h] = (S[h] @ K[h]^T) / sqrt(DH) -> attn region (pre-softmax)
    {
        dim3 grid(NKNOW / BN, NSENT / BM, NHEADS);
        const float scale = 0.08838834764831845f;  // 1/sqrt(128)
        sgemm_kernel<true, false><<<grid, 256>>>(
            Sbuf, Kbuf, nullptr, attn,
            NSENT, NKNOW, DHEAD,
            DHEAD, DHEAD, NKNOW,
            (long)NSENT * DHEAD, (long)NKNOW * DHEAD, 0L, (long)NSENT * NKNOW,
            scale);
    }
    // 4) softmax over the sentence axis, in place
    {
        dim3 grid(NKNOW / 256, NHEADS);
        softmax_cols_kernel<<<grid, 256>>>(attn);
    }
    // 5) fused[n, h*KFDIM + f] = attn[h] @ knowledge
    {
        dim3 grid(KFDIM / BN, NSENT / BM, NHEADS);
        sgemm_kernel<false, false><<<grid, 256>>>(
            attn, knowledge, nullptr, fused,
            NSENT, KFDIM, NKNOW,
            NKNOW, KFDIM, NHEADS * KFDIM,
            (long)NSENT * NKNOW, 0L, 0L, (long)KFDIM,
            1.0f);
    }
}